// round 1
// baseline (speedup 1.0000x reference)
#include <cuda_runtime.h>
#include <cuda_bf16.h>
#include <math.h>

#define BATCH 128
#define OUT   256
#define MB    8      // M branches
#define INS   512    // inner size
#define BI    16     // batch tile
#define BO    16     // out tile
#define KC    128    // k chunk

// z[i,b] = prod_j ( sum_k sigmoid(x[i,j,k] * W[b,j,k]) )
// sigmoid(t) = 0.5*tanh(0.5*t) + 0.5  -> one MUFU.TANH per element
__global__ __launch_bounds__(256) void dnm_main_kernel(
    const float* __restrict__ x,
    const float* __restrict__ w,
    float* __restrict__ z)
{
    __shared__ float xs[KC][BI + 1];   // +1 pad: conflict-free transposed stores
    __shared__ float ws[KC][BO + 1];

    const int tid = threadIdx.x;
    const int tx  = tid & 15;          // batch index within tile
    const int ty  = tid >> 4;          // out index within tile
    const int i0  = blockIdx.x * BI;   // gridDim.x = BATCH/BI = 8
    const int b0  = blockIdx.y * BO;   // gridDim.y = OUT/BO  = 16

    float prod = 1.0f;

    #pragma unroll 1
    for (int j = 0; j < MB; ++j) {
        float s = 0.0f;
        #pragma unroll 1
        for (int kc = 0; kc < INS; kc += KC) {
            // cooperative loads, coalesced in k; store transposed.
            // x is prescaled by 0.5 so inner loop is a single FMUL.
            #pragma unroll
            for (int it = 0; it < (BI * KC) / 256; ++it) {
                int idx = it * 256 + tid;
                int r = idx / KC, c = idx % KC;
                xs[c][r] = 0.5f * x[(size_t)(i0 + r) * (MB * INS) + j * INS + kc + c];
            }
            #pragma unroll
            for (int it = 0; it < (BO * KC) / 256; ++it) {
                int idx = it * 256 + tid;
                int r = idx / KC, c = idx % KC;
                ws[c][r] = w[(size_t)(b0 + r) * (MB * INS) + j * INS + kc + c];
            }
            __syncthreads();

            #pragma unroll 8
            for (int k = 0; k < KC; ++k) {
                float t = xs[k][tx] * ws[k][ty];   // = 0.5 * x * w
                float r;
                asm("tanh.approx.f32 %0, %1;" : "=f"(r) : "f"(t));
                s += r;
            }
            __syncthreads();
        }
        // sum_k sigmoid = 0.5 * sum_k tanh + 0.5 * INS
        prod *= fmaf(0.5f, s, 0.5f * (float)INS);
    }

    z[(size_t)(i0 + tx) * OUT + (b0 + ty)] = prod;
}

// Per-row (dim=1) normalize: z /= sum; mean == 1/256 exactly; std ddof=1.
__global__ __launch_bounds__(OUT) void dnm_norm_kernel(float* __restrict__ z)
{
    __shared__ float red[OUT];
    const int i = blockIdx.x;
    const int b = threadIdx.x;

    float v = z[(size_t)i * OUT + b];

    red[b] = v;
    __syncthreads();
    #pragma unroll
    for (int s = OUT / 2; s > 0; s >>= 1) {
        if (b < s) red[b] += red[b + s];
        __syncthreads();
    }
    float total = red[0];
    __syncthreads();

    float zn = v / total;
    float d  = zn - (1.0f / (float)OUT);

    red[b] = d * d;
    __syncthreads();
    #pragma unroll
    for (int s = OUT / 2; s > 0; s >>= 1) {
        if (b < s) red[b] += red[b + s];
        __syncthreads();
    }
    float stddev = sqrtf(red[0] / (float)(OUT - 1));

    z[(size_t)i * OUT + b] = d / stddev;
}

extern "C" void kernel_launch(void* const* d_in, const int* in_sizes, int n_in,
                              void* d_out, int out_size)
{
    const float* x = (const float*)d_in[0];   // (128, 8, 512)
    const float* w = (const float*)d_in[1];   // (256, 8, 512)
    float* z = (float*)d_out;                 // (128, 256)

    dim3 grid(BATCH / BI, OUT / BO);          // (8, 16) = 128 CTAs
    dnm_main_kernel<<<grid, 256>>>(x, w, z);
    dnm_norm_kernel<<<BATCH, OUT>>>(z);
}

// round 2
// speedup vs baseline: 1.8282x; 1.8282x over previous
#include <cuda_runtime.h>
#include <math.h>

#define BATCH 128
#define OUT   256
#define MB    8      // M branches
#define INS   512    // inner size
#define TI    16     // batch tile
#define TB    16     // out tile
#define KC    256    // k chunk
#define PAD   2
#define KCP   (KC + PAD)

// scratch: S[i][b][j] = sum_k sigmoid(x[i,j,k]*W[b,j,k])
__device__ float g_S[BATCH * OUT * MB];

__device__ __forceinline__ float tanh_approx(float t) {
    float r;
    asm("tanh.approx.f32 %0, %1;" : "=f"(r) : "f"(t));
    return r;
}

// One CTA = one (16 batch x 16 out) tile for ONE branch j.
// sigmoid(t) = 0.5*tanh(0.5 t) + 0.5  -> 1 MUFU per element.
__global__ __launch_bounds__(256) void dnm_main_kernel(
    const float* __restrict__ x,
    const float* __restrict__ w)
{
    __shared__ float xs[TI][KCP];   // [row][k], pad=2 -> conflict-free LDS.64
    __shared__ float ws[TB][KCP];

    const int tid = threadIdx.x;
    const int tx  = tid & 15;          // batch index within tile
    const int ty  = tid >> 4;          // out index within tile
    const int i0  = blockIdx.x * TI;   // 8
    const int b0  = blockIdx.y * TB;   // 16
    const int j   = blockIdx.z;        // 8   -> 1024 CTAs

    float acc0 = 0.0f, acc1 = 0.0f;

    #pragma unroll 1
    for (int kc = 0; kc < INS; kc += KC) {
        // float4 global loads, coalesced; x prescaled by 0.5
        #pragma unroll
        for (int it = 0; it < (TI * KC) / (4 * 256); ++it) {   // 4 iters
            int idx = it * 256 + tid;
            int r = idx >> 6, c = (idx & 63) << 2;
            float4 v = *(const float4*)&x[((size_t)(i0 + r) * MB + j) * INS + kc + c];
            xs[r][c + 0] = 0.5f * v.x; xs[r][c + 1] = 0.5f * v.y;
            xs[r][c + 2] = 0.5f * v.z; xs[r][c + 3] = 0.5f * v.w;
        }
        #pragma unroll
        for (int it = 0; it < (TB * KC) / (4 * 256); ++it) {
            int idx = it * 256 + tid;
            int r = idx >> 6, c = (idx & 63) << 2;
            float4 v = *(const float4*)&w[((size_t)(b0 + r) * MB + j) * INS + kc + c];
            ws[r][c + 0] = v.x; ws[r][c + 1] = v.y;
            ws[r][c + 2] = v.z; ws[r][c + 3] = v.w;
        }
        __syncthreads();

        const float2* xr = (const float2*)&xs[tx][0];   // row offset 258*4 B, 8B-aligned
        const float2* wr = (const float2*)&ws[ty][0];
        #pragma unroll 8
        for (int k2 = 0; k2 < KC / 2; ++k2) {
            float2 xv = xr[k2];
            float2 wv = wr[k2];
            acc0 += tanh_approx(xv.x * wv.x);
            acc1 += tanh_approx(xv.y * wv.y);
        }
        __syncthreads();
    }

    // sum_k sigmoid = 0.5 * sum_k tanh + 0.5 * INS
    float S = fmaf(0.5f, acc0 + acc1, 0.5f * (float)INS);
    g_S[((size_t)(i0 + tx) * OUT + (b0 + ty)) * MB + j] = S;
}

// Per-row normalize with fused product-of-branches.
// zn = v/total has mean exactly 1/256; ddof=1 var = (sum zn^2 - 1/256)/255.
__global__ __launch_bounds__(OUT) void dnm_norm_kernel(float* __restrict__ out)
{
    const int i = blockIdx.x;
    const int b = threadIdx.x;

    const float* sp = &g_S[((size_t)i * OUT + b) * MB];
    float4 a = *(const float4*)sp;
    float4 c = *(const float4*)(sp + 4);
    float v = ((a.x * a.y) * (a.z * a.w)) * ((c.x * c.y) * (c.z * c.w));

    // scale: v ~ 256^8 = 2^64, so v^2 would overflow f32. Stats are
    // scale-invariant after the /total, so work with vs = v * 2^-64.
    float vs = v * 0x1p-64f;

    float s1 = vs, s2 = vs * vs;
    #pragma unroll
    for (int off = 16; off > 0; off >>= 1) {
        s1 += __shfl_xor_sync(0xffffffffu, s1, off);
        s2 += __shfl_xor_sync(0xffffffffu, s2, off);
    }
    __shared__ float r1[8], r2[8];
    if ((b & 31) == 0) { r1[b >> 5] = s1; r2[b >> 5] = s2; }
    __syncthreads();

    float total = 0.0f, sq = 0.0f;
    #pragma unroll
    for (int q = 0; q < 8; ++q) { total += r1[q]; sq += r2[q]; }

    float inv = 1.0f / total;
    float zn  = vs * inv;
    float var = (sq * inv * inv - 1.0f / 256.0f) * (1.0f / 255.0f);
    out[(size_t)i * OUT + b] = (zn - 1.0f / 256.0f) * rsqrtf(var);
}

extern "C" void kernel_launch(void* const* d_in, const int* in_sizes, int n_in,
                              void* d_out, int out_size)
{
    const float* x = (const float*)d_in[0];   // (128, 8, 512)
    const float* w = (const float*)d_in[1];   // (256, 8, 512)
    float* z = (float*)d_out;                 // (128, 256)

    dim3 grid(BATCH / TI, OUT / TB, MB);      // (8, 16, 8) = 1024 CTAs
    dnm_main_kernel<<<grid, 256>>>(x, w);
    dnm_norm_kernel<<<BATCH, OUT>>>(z);
}

// round 4
// speedup vs baseline: 2.0411x; 1.1164x over previous
#include <cuda_runtime.h>
#include <cuda_fp16.h>
#include <math.h>

#define BATCH 128
#define OUT   256
#define MB    8      // M branches
#define INS   512    // inner size (full K in smem, f16)
#define TI    16     // batch tile
#define TB    16     // out tile
#define KP    (INS + 4)   // pad 4 halves (8B) -> conflict-free LDS.64

// scratch: S[i][b][j] = sum_k sigmoid(x[i,j,k]*W[b,j,k])
__device__ float g_S[BATCH * OUT * MB];

__device__ __forceinline__ __half2 tanh_h2(__half2 v) {
    unsigned r, a = *(unsigned*)&v;
    asm("tanh.approx.f16x2 %0, %1;" : "=r"(r) : "r"(a));
    return *(__half2*)&r;
}

// One CTA = one (16 x 16) tile of ONE branch j, full K.
// sigmoid(u) = 0.5 + 0.5*tanh(u/2); x prescaled by 0.5 at f16-convert time.
// tanh.approx.f16x2: 2 elements per MUFU slot.
__global__ __launch_bounds__(256) void dnm_main_kernel(
    const float* __restrict__ x,
    const float* __restrict__ w)
{
    __shared__ __half xs[TI][KP];
    __shared__ __half ws[TB][KP];

    const int tid = threadIdx.x;
    const int tx  = tid & 15;
    const int ty  = tid >> 4;
    const int i0  = blockIdx.x * TI;
    const int b0  = blockIdx.y * TB;
    const int j   = blockIdx.z;        // 1024 CTAs total

    // ---- load + f32->f16 convert (x scaled by 0.5) ----
    #pragma unroll
    for (int it = 0; it < (TI * INS) / (4 * 256); ++it) {
        int idx = it * 256 + tid;
        int r = idx >> 7, c = (idx & 127) << 2;   // 128 float4 per row
        float4 v = *(const float4*)&x[((size_t)(i0 + r) * MB + j) * INS + c];
        __half2 h0 = __floats2half2_rn(0.5f * v.x, 0.5f * v.y);
        __half2 h1 = __floats2half2_rn(0.5f * v.z, 0.5f * v.w);
        *(__half2*)&xs[r][c]     = h0;
        *(__half2*)&xs[r][c + 2] = h1;
    }
    #pragma unroll
    for (int it = 0; it < (TB * INS) / (4 * 256); ++it) {
        int idx = it * 256 + tid;
        int r = idx >> 7, c = (idx & 127) << 2;
        float4 v = *(const float4*)&w[((size_t)(b0 + r) * MB + j) * INS + c];
        __half2 h0 = __floats2half2_rn(v.x, v.y);
        __half2 h1 = __floats2half2_rn(v.z, v.w);
        *(__half2*)&ws[r][c]     = h0;
        *(__half2*)&ws[r][c + 2] = h1;
    }
    __syncthreads();

    // ---- main loop: 4 elements / lane / iter ----
    float acc0 = 0.0f, acc1 = 0.0f;
    const __half* xr = &xs[tx][0];
    const __half* wr = &ws[ty][0];

    #pragma unroll 16
    for (int k = 0; k < INS; k += 4) {
        uint2 xv = *(const uint2*)&xr[k];      // 4 halves of x*0.5
        uint2 wv = *(const uint2*)&wr[k];
        __half2 t01 = __hmul2(*(__half2*)&xv.x, *(__half2*)&wv.x);
        __half2 t23 = __hmul2(*(__half2*)&xv.y, *(__half2*)&wv.y);
        __half2 h01 = tanh_h2(t01);
        __half2 h23 = tanh_h2(t23);
        __half2 s   = __hadd2(h01, h23);       // |s| <= 2, rounding negligible
        acc0 += __low2float(s);
        acc1 += __high2float(s);
    }

    // sum_k sigmoid = 0.5 * sum_k tanh + 256
    float S = fmaf(0.5f, acc0 + acc1, 0.5f * (float)INS);
    g_S[((size_t)(i0 + tx) * OUT + (b0 + ty)) * MB + j] = S;
}

// Per-row normalize with fused product-of-branches.
// zn = v/total has mean exactly 1/256; ddof=1 var = (sum zn^2 - 1/256)/255.
__global__ __launch_bounds__(OUT) void dnm_norm_kernel(float* __restrict__ out)
{
    const int i = blockIdx.x;
    const int b = threadIdx.x;

    const float* sp = &g_S[((size_t)i * OUT + b) * MB];
    float4 a = *(const float4*)sp;
    float4 c = *(const float4*)(sp + 4);
    float v = ((a.x * a.y) * (a.z * a.w)) * ((c.x * c.y) * (c.z * c.w));

    // v ~ 256^8 = 2^64 -> scale before squaring (stats are scale-invariant)
    float vs = v * 0x1p-64f;

    float s1 = vs, s2 = vs * vs;
    #pragma unroll
    for (int off = 16; off > 0; off >>= 1) {
        s1 += __shfl_xor_sync(0xffffffffu, s1, off);
        s2 += __shfl_xor_sync(0xffffffffu, s2, off);
    }
    __shared__ float r1[8], r2[8];
    if ((b & 31) == 0) { r1[b >> 5] = s1; r2[b >> 5] = s2; }
    __syncthreads();

    float total = 0.0f, sq = 0.0f;
    #pragma unroll
    for (int q = 0; q < 8; ++q) { total += r1[q]; sq += r2[q]; }

    float inv = 1.0f / total;
    float zn  = vs * inv;
    float var = (sq * inv * inv - 1.0f / 256.0f) * (1.0f / 255.0f);
    out[(size_t)i * OUT + b] = (zn - 1.0f / 256.0f) * rsqrtf(var);
}

extern "C" void kernel_launch(void* const* d_in, const int* in_sizes, int n_in,
                              void* d_out, int out_size)
{
    const float* x = (const float*)d_in[0];   // (128, 8, 512)
    const float* w = (const float*)d_in[1];   // (256, 8, 512)
    float* z = (float*)d_out;                 // (128, 256)

    dim3 grid(BATCH / TI, OUT / TB, MB);      // (8, 16, 8) = 1024 CTAs
    dnm_main_kernel<<<grid, 256>>>(x, w);
    dnm_norm_kernel<<<BATCH, OUT>>>(z);
}